// round 1
// baseline (speedup 1.0000x reference)
#include <cuda_runtime.h>
#include <math.h>

#define NN 100000
#define NE 3200000
#define H  256
#define NC 40
#define NL 8
#define MPAD 100096   // 782 * 128

// ---------------- scratch (device globals; no allocation allowed) ----------
__device__ int   g_deg[NN];
__device__ int   g_cur[NN];
__device__ int   g_rowptr[NN + 1];
__device__ int   g_bsums[128];
__device__ int   g_csrc[NE];
__device__ float g_cw[NE];
__device__ float g_h0[MPAD * H];
__device__ float g_h [MPAD * H];
__device__ float g_hi[MPAD * H];
__device__ float g_d0[MPAD * H];
__device__ float g_d1[MPAD * H];
__device__ float g_wd[NL * H * H];

// ---------------- CSR build ------------------------------------------------
__global__ void k_zero() {
    int i = blockIdx.x * blockDim.x + threadIdx.x;
    if (i < NN) { g_deg[i] = 0; g_cur[i] = 0; }
}

__global__ void k_hist(const int* __restrict__ dst) {
    int e = blockIdx.x * blockDim.x + threadIdx.x;
    if (e < NE) atomicAdd(&g_deg[dst[e]], 1);
}

// block scans 1024 elems (256 thr x 4)
__global__ void k_scan1() {
    __shared__ int sh[256];
    int b = blockIdx.x, t = threadIdx.x;
    int base = b * 1024 + t * 4;
    int v[4], loc[4];
#pragma unroll
    for (int j = 0; j < 4; j++) { int idx = base + j; v[j] = (idx < NN) ? g_deg[idx] : 0; }
    loc[0] = v[0];
#pragma unroll
    for (int j = 1; j < 4; j++) loc[j] = loc[j - 1] + v[j];
    sh[t] = loc[3];
    __syncthreads();
    for (int off = 1; off < 256; off <<= 1) {
        int x = (t >= off) ? sh[t - off] : 0;
        __syncthreads();
        sh[t] += x;
        __syncthreads();
    }
    int pre = (t > 0) ? sh[t - 1] : 0;
#pragma unroll
    for (int j = 0; j < 4; j++) { int idx = base + j; if (idx < NN) g_rowptr[idx + 1] = pre + loc[j]; }
    if (t == 255) g_bsums[b] = sh[255];
}

__global__ void k_scan2(int nb) {
    __shared__ int sh[128];
    int t = threadIdx.x;
    sh[t] = (t < nb) ? g_bsums[t] : 0;
    __syncthreads();
    for (int off = 1; off < 128; off <<= 1) {
        int x = (t >= off) ? sh[t - off] : 0;
        __syncthreads();
        sh[t] += x;
        __syncthreads();
    }
    g_bsums[t] = sh[t];
}

__global__ void k_scan3() {
    int b = blockIdx.x, t = threadIdx.x;
    int add = (b > 0) ? g_bsums[b - 1] : 0;
#pragma unroll
    for (int j = 0; j < 4; j++) {
        int idx = b * 1024 + t * 4 + j;
        if (idx < NN) g_rowptr[idx + 1] += add;
    }
    if (b == 0 && t == 0) g_rowptr[0] = 0;
}

__global__ void k_scatter(const int* __restrict__ src, const int* __restrict__ dst,
                          const float* __restrict__ w) {
    int e = blockIdx.x * blockDim.x + threadIdx.x;
    if (e < NE) {
        int d = dst[e];
        int pos = g_rowptr[d] + atomicAdd(&g_cur[d], 1);
        g_csrc[pos] = src[e];
        g_cw[pos] = w[e];
    }
}

// Wd_eff[i] = dyn_w[i][:256] - dyn_w[i][256:]
__global__ void k_wd(const float* __restrict__ dynw) {
    int i = blockIdx.x * blockDim.x + threadIdx.x;
    if (i < NL * H * H) {
        int layer = i / (H * H);
        int rem = i % (H * H);
        g_wd[i] = dynw[layer * 2 * H * H + rem] - dynw[layer * 2 * H * H + H * H + rem];
    }
}

// ---------------- GEMM: C[MPAD,256-slice] = [A1|A2] @ B, fused epilogues ---
// BM=128 BN=64 BK=16, 256 threads, 8x4 per thread.
// MODE 0: fc   : v = relu(acc + bias[col]);           C=C2=C3=v
// MODE 1: conv : v = relu(theta*acc + (1-theta)*(0.9*hi + 0.1*h0) + h); C=v
// MODE 2: dyn  : v = relu(acc + bias[col]) + res*h0;  C=v
template <int MODE>
__global__ void __launch_bounds__(256) k_gemm(
    const float* __restrict__ A1, const float* __restrict__ A2,
    int lda, int K, int K1,
    const float* __restrict__ B,
    float* __restrict__ C,
    const float* __restrict__ bias,
    const float* __restrict__ Ehi, const float* __restrict__ Eh0, const float* __restrict__ Eh,
    float theta, float res_scale,
    float* __restrict__ C2, float* __restrict__ C3)
{
    __shared__ float As[16][132];  // transposed, padded (16B-aligned rows: 132*4=528=33*16)
    __shared__ float Bs[16][64];

    int t = threadIdx.x;
    int tx = t & 15, ty = t >> 4;
    int bm0 = blockIdx.y * 128;
    int bn0 = blockIdx.x * 64;

    float acc[8][4];
#pragma unroll
    for (int i = 0; i < 8; i++)
#pragma unroll
        for (int j = 0; j < 4; j++) acc[i][j] = 0.f;

    for (int k0 = 0; k0 < K; k0 += 16) {
#pragma unroll
        for (int p = 0; p < 2; p++) {
            int idx = t + 256 * p;
            int r = idx >> 2, c4 = idx & 3;
            int grow = bm0 + r;
            int kcol = k0 + c4 * 4;
            const float* Ap = A1;
            if (kcol >= K1) { Ap = A2; kcol -= K1; }
            float4 v = make_float4(0.f, 0.f, 0.f, 0.f);
            if (grow < NN) v = *(const float4*)(Ap + (size_t)grow * lda + kcol);
            As[c4 * 4 + 0][r] = v.x;
            As[c4 * 4 + 1][r] = v.y;
            As[c4 * 4 + 2][r] = v.z;
            As[c4 * 4 + 3][r] = v.w;
        }
        {
            int br = t >> 4, bc = (t & 15) * 4;
            *(float4*)&Bs[br][bc] = *(const float4*)(B + (size_t)(k0 + br) * H + bn0 + bc);
        }
        __syncthreads();
#pragma unroll
        for (int k = 0; k < 16; k++) {
            float4 a0 = *(const float4*)&As[k][ty * 8];
            float4 a1 = *(const float4*)&As[k][ty * 8 + 4];
            float4 b4 = *(const float4*)&Bs[k][tx * 4];
            float ar[8] = {a0.x, a0.y, a0.z, a0.w, a1.x, a1.y, a1.z, a1.w};
            float br4[4] = {b4.x, b4.y, b4.z, b4.w};
#pragma unroll
            for (int i = 0; i < 8; i++)
#pragma unroll
                for (int j = 0; j < 4; j++) acc[i][j] += ar[i] * br4[j];
        }
        __syncthreads();
    }

#pragma unroll
    for (int i = 0; i < 8; i++) {
        int row = bm0 + ty * 8 + i;
        if (row >= NN) continue;
        size_t rb = (size_t)row * H;
#pragma unroll
        for (int j = 0; j < 4; j++) {
            int col = bn0 + tx * 4 + j;
            size_t idx = rb + col;
            float v = acc[i][j];
            if (MODE == 0) {
                v = fmaxf(v + bias[col], 0.f);
                C[idx] = v; C2[idx] = v; C3[idx] = v;
            } else if (MODE == 1) {
                float r2 = 0.9f * Ehi[idx] + 0.1f * Eh0[idx];
                v = fmaxf(theta * v + (1.f - theta) * r2 + Eh[idx], 0.f);
                C[idx] = v;
            } else {
                v = fmaxf(v + bias[col], 0.f) + res_scale * Eh0[idx];
                C[idx] = v;
            }
        }
    }
}

// ---------------- SpMM: hi[n,:] = sum_e w_e * h[src_e,:], warp per node ----
__global__ void __launch_bounds__(256) k_spmm(const float* __restrict__ h,
                                              float* __restrict__ hi) {
    int wid = (blockIdx.x * blockDim.x + threadIdx.x) >> 5;
    int lane = threadIdx.x & 31;
    if (wid >= NN) return;
    int s0 = g_rowptr[wid], s1 = g_rowptr[wid + 1];
    float4 a0 = make_float4(0.f, 0.f, 0.f, 0.f);
    float4 a1 = make_float4(0.f, 0.f, 0.f, 0.f);
    const float4* h4 = (const float4*)h;
    for (int e = s0; e < s1; e++) {
        int s = g_csrc[e];
        float w = g_cw[e];
        const float4* hp = h4 + (size_t)s * 64;
        float4 v0 = __ldg(hp + lane);
        float4 v1 = __ldg(hp + lane + 32);
        a0.x += w * v0.x; a0.y += w * v0.y; a0.z += w * v0.z; a0.w += w * v0.w;
        a1.x += w * v1.x; a1.y += w * v1.y; a1.z += w * v1.z; a1.w += w * v1.w;
    }
    float4* op = (float4*)hi + (size_t)wid * 64;
    op[lane] = a0;
    op[lane + 32] = a1;
}

// ---------------- LN(h) + LN(d) -> cross, warp per row ---------------------
__device__ __forceinline__ float warp_sum(float v) {
#pragma unroll
    for (int off = 16; off; off >>= 1) v += __shfl_xor_sync(0xffffffffu, v, off);
    return v;
}

__global__ void __launch_bounds__(256) k_cross(
    const float* __restrict__ h, const float* __restrict__ d,
    const float* __restrict__ g1, const float* __restrict__ b1,
    const float* __restrict__ g2, const float* __restrict__ b2,
    float* __restrict__ crossbuf, float* __restrict__ cross_out)
{
    int row = blockIdx.x * 8 + (threadIdx.x >> 5);
    int lane = threadIdx.x & 31;
    if (row >= NN) return;
    size_t rb = (size_t)row * H;
    float hv[8], dv[8];
#pragma unroll
    for (int r = 0; r < 8; r++) {
        int k = lane + 32 * r;
        hv[r] = h[rb + k];
        dv[r] = d[rb + k];
    }
    float sh = 0.f, sd = 0.f;
#pragma unroll
    for (int r = 0; r < 8; r++) { sh += hv[r]; sd += dv[r]; }
    sh = warp_sum(sh); sd = warp_sum(sd);
    float m1 = sh * (1.f / 256.f), m2 = sd * (1.f / 256.f);
    float q1 = 0.f, q2 = 0.f;
#pragma unroll
    for (int r = 0; r < 8; r++) {
        float e1 = hv[r] - m1; q1 += e1 * e1;
        float e2 = dv[r] - m2; q2 += e2 * e2;
    }
    q1 = warp_sum(q1); q2 = warp_sum(q2);
    float i1 = rsqrtf(q1 * (1.f / 256.f) + 1e-6f);
    float i2 = rsqrtf(q2 * (1.f / 256.f) + 1e-6f);
#pragma unroll
    for (int r = 0; r < 8; r++) {
        int k = lane + 32 * r;
        float v = g1[k] * (hv[r] - m1) * i1 + b1[k] + g2[k] * (dv[r] - m2) * i2 + b2[k];
        crossbuf[rb + k] = v;
        if (cross_out) cross_out[rb + k] = v;
    }
}

// ---------------- out = log_softmax(cross @ Wout + bout), warp per row -----
__global__ void __launch_bounds__(256) k_out(
    const float* __restrict__ cross, const float* __restrict__ Wout,
    const float* __restrict__ bout, float* __restrict__ out)
{
    __shared__ float Ws[256 * 41];
    __shared__ float bs[NC];
    int t = threadIdx.x;
    for (int i = t; i < 256 * NC; i += 256) {
        int k = i / NC, c = i - k * NC;
        Ws[k * 41 + c] = Wout[i];
    }
    if (t < NC) bs[t] = bout[t];
    __syncthreads();

    int row = blockIdx.x * 8 + (t >> 5);
    int lane = t & 31;
    if (row >= NN) return;

    float acc[NC];
#pragma unroll
    for (int c = 0; c < NC; c++) acc[c] = 0.f;
    size_t rb = (size_t)row * H;
#pragma unroll
    for (int r = 0; r < 8; r++) {
        int k = lane + 32 * r;
        float v = cross[rb + k];
        const float* wr = &Ws[k * 41];
#pragma unroll
        for (int c = 0; c < NC; c++) acc[c] += v * wr[c];
    }
#pragma unroll
    for (int c = 0; c < NC; c++)
#pragma unroll
        for (int off = 16; off; off >>= 1) acc[c] += __shfl_xor_sync(0xffffffffu, acc[c], off);

    float m = -1e30f;
#pragma unroll
    for (int c = 0; c < NC; c++) { acc[c] += bs[c]; m = fmaxf(m, acc[c]); }
    float s = 0.f;
#pragma unroll
    for (int c = 0; c < NC; c++) s += expf(acc[c] - m);
    float lse = m + logf(s);
    float* o = out + (size_t)row * NC;
#pragma unroll
    for (int c = 0; c < NC; c++)
        if ((c & 31) == lane) o[c] = acc[c] - lse;
}

// ---------------- launch ---------------------------------------------------
extern "C" void kernel_launch(void* const* d_in, const int* in_sizes, int n_in,
                              void* d_out, int out_size)
{
    const float* x     = (const float*)d_in[0];
    const int*   esrc  = (const int*)d_in[1];
    const int*   edst  = (const int*)d_in[2];
    const float* ew    = (const float*)d_in[3];
    const float* Wfc   = (const float*)d_in[4];
    const float* bfc   = (const float*)d_in[5];
    const float* convw = (const float*)d_in[6];
    const float* dynw  = (const float*)d_in[7];
    const float* dynb  = (const float*)d_in[8];
    const float* g1    = (const float*)d_in[9];
    const float* b1    = (const float*)d_in[10];
    const float* g2    = (const float*)d_in[11];
    const float* b2    = (const float*)d_in[12];
    const float* Wout  = (const float*)d_in[13];
    const float* bout  = (const float*)d_in[14];
    float* out = (float*)d_out;

    float *h0, *h, *hi, *d0, *d1, *wd;
    cudaGetSymbolAddress((void**)&h0, g_h0);
    cudaGetSymbolAddress((void**)&h,  g_h);
    cudaGetSymbolAddress((void**)&hi, g_hi);
    cudaGetSymbolAddress((void**)&d0, g_d0);
    cudaGetSymbolAddress((void**)&d1, g_d1);
    cudaGetSymbolAddress((void**)&wd, g_wd);

    // CSR build
    k_zero<<<(NN + 255) / 256, 256>>>();
    k_hist<<<NE / 256, 256>>>(edst);
    k_scan1<<<98, 256>>>();
    k_scan2<<<1, 128>>>(98);
    k_scan3<<<98, 256>>>();
    k_scatter<<<NE / 256, 256>>>(esrc, edst, ew);
    k_wd<<<(NL * H * H + 255) / 256, 256>>>(dynw);

    dim3 grid(H / 64, MPAD / 128);

    // h0 = relu(x @ Wfc + bfc); h = h0; d = h0
    k_gemm<0><<<grid, 256>>>(x, (const float*)nullptr, 512, 512, 1 << 30, Wfc, h0,
                             bfc, nullptr, nullptr, nullptr, 0.f, 0.f, h, d0);

    for (int i = 0; i < NL; i++) {
        k_spmm<<<NN / 8, 256>>>(h, hi);
        float theta = logf(0.5f / (float)(i + 1) + 1.0f);
        // h = relu(theta*([hi|h0]@convw_i) + (1-theta)*(0.9*hi+0.1*h0) + h)
        k_gemm<1><<<grid, 256>>>(hi, h0, 256, 512, 256, convw + (size_t)i * 2 * H * H, h,
                                 nullptr, hi, h0, h, theta, 0.f, nullptr, nullptr);
        // d_next = relu(d @ Wd_eff_i + dynb_i) + (i>0 ? 0.1*h0 : 0)
        const float* din = (i & 1) ? d1 : d0;
        float*       dou = (i & 1) ? d0 : d1;
        k_gemm<2><<<grid, 256>>>(din, (const float*)nullptr, 256, 256, 1 << 30,
                                 wd + (size_t)i * H * H, dou, dynb + (size_t)i * H,
                                 nullptr, h0, nullptr, 0.f, (i > 0) ? 0.1f : 0.f,
                                 nullptr, nullptr);
    }
    // final d is in d0 (layer 7 writes d0)

    float* cross_out_ptr = (out_size >= NN * (NC + H)) ? (out + (size_t)NN * NC) : nullptr;
    k_cross<<<NN / 8, 256>>>(h, d0, g1, b1, g2, b2, d1 /*scratch*/, cross_out_ptr);
    k_out<<<NN / 8, 256>>>(d1, Wout, bout, out);
}

// round 4
// speedup vs baseline: 1.3577x; 1.3577x over previous
#include <cuda_runtime.h>
#include <cuda_bf16.h>
#include <math.h>
#include <stdint.h>

#define NN 100000
#define NE 3200000
#define H  256
#define NC 40
#define NL 8
#define MPAD 100096          // 782 * 128
#define GRID_M 782

// ---------------- device scratch (no allocations allowed) ------------------
__device__ int   g_deg[NN];
__device__ int   g_cur[NN];
__device__ int   g_rowptr[NN + 1];
__device__ int   g_bsums[128];
__device__ int   g_csrc[NE];
__device__ float g_cw[NE];

__device__ float g_h0f[MPAD * H];
__device__ float g_hf [MPAD * H];
__device__ float g_hif[MPAD * H];
__device__ float g_df [MPAD * H];

__device__ __nv_bfloat16 g_bx_hi[MPAD * 512];
__device__ __nv_bfloat16 g_bx_lo[MPAD * 512];
__device__ __nv_bfloat16 g_bh0_hi[MPAD * H];
__device__ __nv_bfloat16 g_bh0_lo[MPAD * H];
__device__ __nv_bfloat16 g_bhi_hi[MPAD * H];
__device__ __nv_bfloat16 g_bhi_lo[MPAD * H];
__device__ __nv_bfloat16 g_bdA_hi[MPAD * H];
__device__ __nv_bfloat16 g_bdA_lo[MPAD * H];
__device__ __nv_bfloat16 g_bdB_hi[MPAD * H];
__device__ __nv_bfloat16 g_bdB_lo[MPAD * H];

// weights, pre-transposed to [N=256][K] row-major, bf16 split
__device__ __nv_bfloat16 g_wt9_hi[9 * H * 512];   // fc + 8 conv (K=512)
__device__ __nv_bfloat16 g_wt9_lo[9 * H * 512];
__device__ __nv_bfloat16 g_wtd_hi[NL * H * H];    // dyn effective (K=256)
__device__ __nv_bfloat16 g_wtd_lo[NL * H * H];

// ---------------- helpers --------------------------------------------------
__device__ __forceinline__ uint32_t smem_u32(const void* p) {
    uint32_t a;
    asm("{ .reg .u64 t; cvta.to.shared.u64 t, %1; cvt.u32.u64 %0, t; }" : "=r"(a) : "l"(p));
    return a;
}
#define SW128(o) ((o) ^ (((o) >> 3) & 0x70))

__device__ __forceinline__ void cpasync16(uint32_t dst, const void* src, int srcsize) {
    uint64_t g = __cvta_generic_to_global(src);
    asm volatile("cp.async.cg.shared.global [%0], [%1], 16, %2;"
                 :: "r"(dst), "l"(g), "r"(srcsize) : "memory");
}
#define CP_COMMIT() asm volatile("cp.async.commit_group;" ::: "memory")
#define CP_WAIT1()  asm volatile("cp.async.wait_group 1;" ::: "memory")
#define CP_WAIT0()  asm volatile("cp.async.wait_group 0;" ::: "memory")

__device__ __forceinline__ void ldx4(uint32_t* r, uint32_t addr) {
    asm volatile("ldmatrix.sync.aligned.m8n8.x4.shared.b16 {%0,%1,%2,%3}, [%4];"
                 : "=r"(r[0]), "=r"(r[1]), "=r"(r[2]), "=r"(r[3]) : "r"(addr));
}
__device__ __forceinline__ void ldx2(uint32_t* r, uint32_t addr) {
    asm volatile("ldmatrix.sync.aligned.m8n8.x2.shared.b16 {%0,%1}, [%2];"
                 : "=r"(r[0]), "=r"(r[1]) : "r"(addr));
}
__device__ __forceinline__ void mma16816(float* c, const uint32_t* a, const uint32_t* b) {
    asm volatile("mma.sync.aligned.m16n8k16.row.col.f32.bf16.bf16.f32 "
                 "{%0,%1,%2,%3}, {%4,%5,%6,%7}, {%8,%9}, {%0,%1,%2,%3};"
                 : "+f"(c[0]), "+f"(c[1]), "+f"(c[2]), "+f"(c[3])
                 : "r"(a[0]), "r"(a[1]), "r"(a[2]), "r"(a[3]), "r"(b[0]), "r"(b[1]));
}

// smem: two 64KB buffers: [Ahi 16K][Alo 16K][Bhi 16K][Blo 16K]
#define BUFSZ 65536
#define SMEM_TOTAL (2 * BUFSZ)

// ---------------- CSR build ------------------------------------------------
__global__ void k_zero() {
    int i = blockIdx.x * blockDim.x + threadIdx.x;
    if (i < NN) { g_deg[i] = 0; g_cur[i] = 0; }
}
__global__ void k_hist(const int* __restrict__ dst) {
    int e = blockIdx.x * blockDim.x + threadIdx.x;
    if (e < NE) atomicAdd(&g_deg[dst[e]], 1);
}
__global__ void k_scan1() {
    __shared__ int sh[256];
    int b = blockIdx.x, t = threadIdx.x;
    int base = b * 1024 + t * 4;
    int v[4], loc[4];
#pragma unroll
    for (int j = 0; j < 4; j++) { int idx = base + j; v[j] = (idx < NN) ? g_deg[idx] : 0; }
    loc[0] = v[0];
#pragma unroll
    for (int j = 1; j < 4; j++) loc[j] = loc[j - 1] + v[j];
    sh[t] = loc[3];
    __syncthreads();
    for (int off = 1; off < 256; off <<= 1) {
        int x = (t >= off) ? sh[t - off] : 0;
        __syncthreads();
        sh[t] += x;
        __syncthreads();
    }
    int pre = (t > 0) ? sh[t - 1] : 0;
#pragma unroll
    for (int j = 0; j < 4; j++) { int idx = base + j; if (idx < NN) g_rowptr[idx + 1] = pre + loc[j]; }
    if (t == 255) g_bsums[b] = sh[255];
}
__global__ void k_scan2(int nb) {
    __shared__ int sh[128];
    int t = threadIdx.x;
    sh[t] = (t < nb) ? g_bsums[t] : 0;
    __syncthreads();
    for (int off = 1; off < 128; off <<= 1) {
        int x = (t >= off) ? sh[t - off] : 0;
        __syncthreads();
        sh[t] += x;
        __syncthreads();
    }
    g_bsums[t] = sh[t];
}
__global__ void k_scan3() {
    int b = blockIdx.x, t = threadIdx.x;
    int add = (b > 0) ? g_bsums[b - 1] : 0;
#pragma unroll
    for (int j = 0; j < 4; j++) {
        int idx = b * 1024 + t * 4 + j;
        if (idx < NN) g_rowptr[idx + 1] += add;
    }
    if (b == 0 && t == 0) g_rowptr[0] = 0;
}
__global__ void k_scatter(const int* __restrict__ src, const int* __restrict__ dst,
                          const float* __restrict__ w) {
    int e = blockIdx.x * blockDim.x + threadIdx.x;
    if (e < NE) {
        int d = dst[e];
        int pos = g_rowptr[d] + atomicAdd(&g_cur[d], 1);
        g_csrc[pos] = src[e];
        g_cw[pos] = w[e];
    }
}

// ---------------- weight prep (transpose + bf16 split) ---------------------
__device__ __forceinline__ void bsplit(float v, __nv_bfloat16& hi, __nv_bfloat16& lo) {
    hi = __float2bfloat16_rn(v);
    lo = __float2bfloat16_rn(v - __bfloat162float(hi));
}
__global__ void k_wprep9(const float* __restrict__ Wfc, const float* __restrict__ convw) {
    int idx = blockIdx.x * blockDim.x + threadIdx.x;
    if (idx >= 9 * 512 * 256) return;
    int m = idx / (512 * 256);
    int r = idx - m * 512 * 256;
    int k = r / 256, n = r - k * 256;
    float v = (m == 0) ? Wfc[r] : convw[(m - 1) * 512 * 256 + r];
    __nv_bfloat16 hi, lo; bsplit(v, hi, lo);
    size_t o = (size_t)m * 256 * 512 + (size_t)n * 512 + k;
    g_wt9_hi[o] = hi; g_wt9_lo[o] = lo;
}
__global__ void k_wprepd(const float* __restrict__ dynw) {
    int idx = blockIdx.x * blockDim.x + threadIdx.x;
    if (idx >= NL * 256 * 256) return;
    int i = idx / (256 * 256);
    int r = idx - i * 256 * 256;
    int k = r / 256, n = r - k * 256;
    const float* base = dynw + (size_t)i * 512 * 256;
    float v = base[k * 256 + n] - base[(k + 256) * 256 + n];
    __nv_bfloat16 hi, lo; bsplit(v, hi, lo);
    size_t o = (size_t)i * 256 * 256 + (size_t)n * 256 + k;
    g_wtd_hi[o] = hi; g_wtd_lo[o] = lo;
}
__global__ void k_convx(const float* __restrict__ x) {
    int idx = blockIdx.x * blockDim.x + threadIdx.x;
    if (idx >= NN * 512) return;
    __nv_bfloat16 hi, lo; bsplit(x[idx], hi, lo);
    g_bx_hi[idx] = hi; g_bx_lo[idx] = lo;
}

// ---------------- warp-MMA GEMM with fused epilogues ------------------------
// C[M,256] = A[M,K] @ W^T, bf16 split (AhiBhi + AhiBlo + AloBhi), fp32 acc.
// MODE 0 fc  : v=relu(acc+bias); write C(hf), C2(h0f), Chi/Clo(bh0)
// MODE 1 conv: v=relu(theta*acc+(1-theta)*(0.9*Ehi+0.1*Eh0)+Eh); write C
// MODE 2 dyn : v=relu(acc+bias)+res*Eh0; write C(df), Chi/Clo
template <int MODE>
__global__ void __launch_bounds__(256, 1)
k_gemm_mma(const __nv_bfloat16* __restrict__ A1h, const __nv_bfloat16* __restrict__ A1l, int s1,
           const __nv_bfloat16* __restrict__ A2h, const __nv_bfloat16* __restrict__ A2l, int s2,
           int K1, int K,
           const __nv_bfloat16* __restrict__ Bh, const __nv_bfloat16* __restrict__ Bl,
           float* __restrict__ C, const float* __restrict__ bias,
           const float* __restrict__ Ehi, const float* __restrict__ Eh0, const float* __restrict__ Eh,
           float theta, float res_scale,
           __nv_bfloat16* __restrict__ Chi, __nv_bfloat16* __restrict__ Clo,
           float* __restrict__ C2)
{
    extern __shared__ char smc[];
    uint32_t sb = smem_u32(smc);
    int t = threadIdx.x, lane = t & 31, wid = t >> 5;
    int widm = wid >> 2, widn = wid & 3;   // 2 x 4 warp grid
    int bn0 = blockIdx.x * 128;
    int bm0 = blockIdx.y * 128;

    float acc[4][4][4];
#pragma unroll
    for (int a = 0; a < 4; a++)
#pragma unroll
        for (int b = 0; b < 4; b++)
#pragma unroll
            for (int c = 0; c < 4; c++) acc[a][b][c] = 0.f;

    const int nc = K / 64;

    // ---- loader ----
    auto load_chunk = [&](int ch, int buf) {
        uint32_t bb = sb + buf * BUFSZ;
        int kk0 = ch * 64;
#pragma unroll
        for (int j = 0; j < 4; j++) {
            int idx = t + j * 256;
            int row = idx >> 3, c16 = idx & 7;
            uint32_t d = SW128(row * 128 + c16 * 16);
            // A
            int grow = bm0 + row;
            int kk = kk0 + c16 * 8;
            const __nv_bfloat16 *ph, *pl; int st;
            if (kk < K1) { ph = A1h; pl = A1l; st = s1; }
            else         { ph = A2h; pl = A2l; st = s2; kk -= K1; }
            int pred = 16;
            if (grow >= NN) { grow = 0; pred = 0; }
            cpasync16(bb + d,         ph + (size_t)grow * st + kk, pred);
            cpasync16(bb + 16384 + d, pl + (size_t)grow * st + kk, pred);
            // B (rows always valid; grid covers exactly 256 n)
            int kkb = kk0 + c16 * 8;
            size_t bo = (size_t)(bn0 + row) * K + kkb;
            cpasync16(bb + 32768 + d, Bh + bo, 16);
            cpasync16(bb + 49152 + d, Bl + bo, 16);
        }
        CP_COMMIT();
    };

    // ---- compute ----
    int mi = lane >> 3;
    int arow_off = (lane & 7) + ((mi & 1) << 3);
    int akcol = (mi >> 1) << 4;
    int brow_off = (lane & 7);
    int bkcol = ((lane >> 3) & 1) << 4;

    auto compute_chunk = [&](int buf) {
        uint32_t bb = sb + buf * BUFSZ;
#pragma unroll
        for (int ks = 0; ks < 4; ks++) {
            int kb = ks * 32;
            uint32_t Ah[4][4], Al[4][4], Bh2[4][2], Bl2[4][2];
#pragma unroll
            for (int mt = 0; mt < 4; mt++) {
                int row = widm * 64 + mt * 16 + arow_off;
                uint32_t ad = bb + SW128(row * 128 + kb + akcol);
                ldx4(Ah[mt], ad);
                ldx4(Al[mt], ad + 16384);
            }
#pragma unroll
            for (int nt = 0; nt < 4; nt++) {
                int row = widn * 32 + nt * 8 + brow_off;
                uint32_t bd = bb + 32768 + SW128(row * 128 + kb + bkcol);
                ldx2(Bh2[nt], bd);
                ldx2(Bl2[nt], bd + 16384);
            }
#pragma unroll
            for (int mt = 0; mt < 4; mt++)
#pragma unroll
                for (int nt = 0; nt < 4; nt++) {
                    mma16816(acc[mt][nt], Ah[mt], Bh2[nt]);
                    mma16816(acc[mt][nt], Ah[mt], Bl2[nt]);
                    mma16816(acc[mt][nt], Al[mt], Bh2[nt]);
                }
        }
    };

    load_chunk(0, 0);
    for (int c = 0; c < nc; c++) {
        if (c + 1 < nc) { load_chunk(c + 1, (c + 1) & 1); CP_WAIT1(); }
        else            { CP_WAIT0(); }
        __syncthreads();
        compute_chunk(c & 1);
        __syncthreads();
    }

    // ---- epilogue ----
#pragma unroll
    for (int mt = 0; mt < 4; mt++) {
#pragma unroll
        for (int nt = 0; nt < 4; nt++) {
            int cb = bn0 + widn * 32 + nt * 8 + (lane & 3) * 2;
#pragma unroll
            for (int half = 0; half < 2; half++) {
                int row = bm0 + widm * 64 + mt * 16 + (lane >> 2) + half * 8;
                if (row >= NN) continue;
                size_t rb = (size_t)row * H + cb;
                float v0 = acc[mt][nt][half * 2 + 0];
                float v1 = acc[mt][nt][half * 2 + 1];
                if (MODE == 0) {
                    v0 = fmaxf(v0 + bias[cb], 0.f);
                    v1 = fmaxf(v1 + bias[cb + 1], 0.f);
                } else if (MODE == 1) {
                    float2 e1 = *(const float2*)(Ehi + rb);
                    float2 e2 = *(const float2*)(Eh0 + rb);
                    float2 e3 = *(const float2*)(Eh + rb);
                    v0 = fmaxf(theta * v0 + (1.f - theta) * (0.9f * e1.x + 0.1f * e2.x) + e3.x, 0.f);
                    v1 = fmaxf(theta * v1 + (1.f - theta) * (0.9f * e1.y + 0.1f * e2.y) + e3.y, 0.f);
                } else {
                    float2 e2 = *(const float2*)(Eh0 + rb);
                    v0 = fmaxf(v0 + bias[cb], 0.f) + res_scale * e2.x;
                    v1 = fmaxf(v1 + bias[cb + 1], 0.f) + res_scale * e2.y;
                }
                *(float2*)(C + rb) = make_float2(v0, v1);
                if (MODE == 0) *(float2*)(C2 + rb) = make_float2(v0, v1);
                if (MODE == 0 || MODE == 2) {
                    union { uint32_t u; __nv_bfloat16 b[2]; } ph_, pl_;
                    __nv_bfloat16 h0b = __float2bfloat16_rn(v0);
                    __nv_bfloat16 h1b = __float2bfloat16_rn(v1);
                    ph_.b[0] = h0b; ph_.b[1] = h1b;
                    pl_.b[0] = __float2bfloat16_rn(v0 - __bfloat162float(h0b));
                    pl_.b[1] = __float2bfloat16_rn(v1 - __bfloat162float(h1b));
                    *(uint32_t*)(Chi + rb) = ph_.u;
                    *(uint32_t*)(Clo + rb) = pl_.u;
                }
            }
        }
    }
}

// ---------------- SpMM: hi = A@h (warp per node), writes f32 + bf16 pair ---
__global__ void __launch_bounds__(256) k_spmm(const float* __restrict__ h,
                                              float* __restrict__ hif,
                                              __nv_bfloat16* __restrict__ bhih,
                                              __nv_bfloat16* __restrict__ bhil) {
    int node = (blockIdx.x * blockDim.x + threadIdx.x) >> 5;
    int lane = threadIdx.x & 31;
    if (node >= NN) return;
    int s0 = g_rowptr[node], s1 = g_rowptr[node + 1];
    float4 a0 = make_float4(0.f, 0.f, 0.f, 0.f);
    float4 a1 = make_float4(0.f, 0.f, 0.f, 0.f);
    const float4* h4 = (const float4*)h;
    int e = s0;
    for (; e + 1 < s1; e += 2) {
        int sA = g_csrc[e], sB = g_csrc[e + 1];
        float wA = g_cw[e], wB = g_cw[e + 1];
        const float4* pA = h4 + (size_t)sA * 64;
        const float4* pB = h4 + (size_t)sB * 64;
        float4 vA0 = __ldg(pA + lane), vA1 = __ldg(pA + lane + 32);
        float4 vB0 = __ldg(pB + lane), vB1 = __ldg(pB + lane + 32);
        a0.x += wA * vA0.x + wB * vB0.x; a0.y += wA * vA0.y + wB * vB0.y;
        a0.z += wA * vA0.z + wB * vB0.z; a0.w += wA * vA0.w + wB * vB0.w;
        a1.x += wA * vA1.x + wB * vB1.x; a1.y += wA * vA1.y + wB * vB1.y;
        a1.z += wA * vA1.z + wB * vB1.z; a1.w += wA * vA1.w + wB * vB1.w;
    }
    if (e < s1) {
        int sA = g_csrc[e];
        float wA = g_cw[e];
        const float4* pA = h4 + (size_t)sA * 64;
        float4 vA0 = __ldg(pA + lane), vA1 = __ldg(pA + lane + 32);
        a0.x += wA * vA0.x; a0.y += wA * vA0.y; a0.z += wA * vA0.z; a0.w += wA * vA0.w;
        a1.x += wA * vA1.x; a1.y += wA * vA1.y; a1.z += wA * vA1.z; a1.w += wA * vA1.w;
    }
    float4* op = (float4*)hif + (size_t)node * 64;
    op[lane] = a0;
    op[lane + 32] = a1;
    size_t rb = (size_t)node * H;
    union { uint2 u; __nv_bfloat16 b[4]; } ph_, pl_;
    float va[4] = {a0.x, a0.y, a0.z, a0.w};
#pragma unroll
    for (int i = 0; i < 4; i++) {
        __nv_bfloat16 hb = __float2bfloat16_rn(va[i]);
        ph_.b[i] = hb; pl_.b[i] = __float2bfloat16_rn(va[i] - __bfloat162float(hb));
    }
    *(uint2*)(bhih + rb + lane * 4) = ph_.u;
    *(uint2*)(bhil + rb + lane * 4) = pl_.u;
    float vb[4] = {a1.x, a1.y, a1.z, a1.w};
#pragma unroll
    for (int i = 0; i < 4; i++) {
        __nv_bfloat16 hb = __float2bfloat16_rn(vb[i]);
        ph_.b[i] = hb; pl_.b[i] = __float2bfloat16_rn(vb[i] - __bfloat162float(hb));
    }
    *(uint2*)(bhih + rb + 128 + lane * 4) = ph_.u;
    *(uint2*)(bhil + rb + 128 + lane * 4) = pl_.u;
}

// ---------------- LN cross + output ----------------------------------------
__device__ __forceinline__ float warp_sum(float v) {
#pragma unroll
    for (int off = 16; off; off >>= 1) v += __shfl_xor_sync(0xffffffffu, v, off);
    return v;
}

__global__ void __launch_bounds__(256) k_cross(
    const float* __restrict__ h, const float* __restrict__ d,
    const float* __restrict__ g1, const float* __restrict__ b1,
    const float* __restrict__ g2, const float* __restrict__ b2,
    float* __restrict__ crossbuf, float* __restrict__ cross_out)
{
    int row = blockIdx.x * 8 + (threadIdx.x >> 5);
    int lane = threadIdx.x & 31;
    if (row >= NN) return;
    size_t rb = (size_t)row * H;
    float hv[8], dv[8];
#pragma unroll
    for (int r = 0; r < 8; r++) {
        int k = lane + 32 * r;
        hv[r] = h[rb + k];
        dv[r] = d[rb + k];
    }
    float sh = 0.f, sd = 0.f;
#pragma unroll
    for (int r = 0; r < 8; r++) { sh += hv[r]; sd += dv[r]; }
    sh = warp_sum(sh); sd = warp_sum(sd);
    float m1 = sh * (1.f / 256.f), m2 = sd * (1.f / 256.f);
    float q1 = 0.f, q2 = 0.f;
#pragma unroll
    for (int r = 0; r < 8; r++) {
        float e1 = hv[r] - m1; q1 += e1 * e1;
        float e2 = dv[r] - m2; q2 += e2 * e2;
    }
    q1 = warp_sum(q1); q2 = warp_sum(q2);
    float i1 = rsqrtf(q1 * (1.f / 256.f) + 1e-6f);
    float i2 = rsqrtf(q2 * (1.f / 256.f) + 1e-6f);
#pragma unroll
    for (int r = 0; r < 8; r++) {
        int k = lane + 32 * r;
        float v = g1[k] * (hv[r] - m1) * i1 + b1[k] + g2[k] * (dv[r] - m2) * i2 + b2[k];
        crossbuf[rb + k] = v;
        if (cross_out) cross_out[rb + k] = v;
    }
}

__global__ void __launch_bounds__(256) k_out(
    const float* __restrict__ cross, const float* __restrict__ Wout,
    const float* __restrict__ bout, float* __restrict__ out)
{
    __shared__ float Ws[256 * 41];
    __shared__ float bs[NC];
    int t = threadIdx.x;
    for (int i = t; i < 256 * NC; i += 256) {
        int k = i / NC, c = i - k * NC;
        Ws[k * 41 + c] = Wout[i];
    }
    if (t < NC) bs[t] = bout[t];
    __syncthreads();

    int row = blockIdx.x * 8 + (t >> 5);
    int lane = t & 31;
    if (row >= NN) return;

    float acc[NC];
#pragma unroll
    for (int c = 0; c < NC; c++) acc[c] = 0.f;
    size_t rb = (size_t)row * H;
#pragma unroll
    for (int r = 0; r < 8; r++) {
        int k = lane + 32 * r;
        float v = cross[rb + k];
        const float* wr = &Ws[k * 41];
#pragma unroll
        for (int c = 0; c < NC; c++) acc[c] += v * wr[c];
    }
#pragma unroll
    for (int c = 0; c < NC; c++)
#pragma unroll
        for (int off = 16; off; off >>= 1) acc[c] += __shfl_xor_sync(0xffffffffu, acc[c], off);

    float m = -1e30f;
#pragma unroll
    for (int c = 0; c < NC; c++) { acc[c] += bs[c]; m = fmaxf(m, acc[c]); }
    float s = 0.f;
#pragma unroll
    for (int c = 0; c < NC; c++) s += expf(acc[c] - m);
    float lse = m + logf(s);
    float* o = out + (size_t)row * NC;
#pragma unroll
    for (int c = 0; c < NC; c++)
        if ((c & 31) == lane) o[c] = acc[c] - lse;
}

// ---------------- launch ---------------------------------------------------
extern "C" void kernel_launch(void* const* d_in, const int* in_sizes, int n_in,
                              void* d_out, int out_size)
{
    const float* x     = (const float*)d_in[0];
    const int*   esrc  = (const int*)d_in[1];
    const int*   edst  = (const int*)d_in[2];
    const float* ew    = (const float*)d_in[3];
    const float* Wfc   = (const float*)d_in[4];
    const float* bfc   = (const float*)d_in[5];
    const float* convw = (const float*)d_in[6];
    const float* dynw  = (const float*)d_in[7];
    const float* dynb  = (const float*)d_in[8];
    const float* g1    = (const float*)d_in[9];
    const float* b1    = (const float*)d_in[10];
    const float* g2    = (const float*)d_in[11];
    const float* b2    = (const float*)d_in[12];
    const float* Wout  = (const float*)d_in[13];
    const float* bout  = (const float*)d_in[14];
    float* out = (float*)d_out;

    float *h0f, *hf, *hif, *df;
    cudaGetSymbolAddress((void**)&h0f, g_h0f);
    cudaGetSymbolAddress((void**)&hf,  g_hf);
    cudaGetSymbolAddress((void**)&hif, g_hif);
    cudaGetSymbolAddress((void**)&df,  g_df);
    __nv_bfloat16 *bxh, *bxl, *bh0h, *bh0l, *bhih, *bhil, *bdAh, *bdAl, *bdBh, *bdBl, *w9h, *w9l, *wdh, *wdl;
    cudaGetSymbolAddress((void**)&bxh, g_bx_hi);
    cudaGetSymbolAddress((void**)&bxl, g_bx_lo);
    cudaGetSymbolAddress((void**)&bh0h, g_bh0_hi);
    cudaGetSymbolAddress((void**)&bh0l, g_bh0_lo);
    cudaGetSymbolAddress((void**)&bhih, g_bhi_hi);
    cudaGetSymbolAddress((void**)&bhil, g_bhi_lo);
    cudaGetSymbolAddress((void**)&bdAh, g_bdA_hi);
    cudaGetSymbolAddress((void**)&bdAl, g_bdA_lo);
    cudaGetSymbolAddress((void**)&bdBh, g_bdB_hi);
    cudaGetSymbolAddress((void**)&bdBl, g_bdB_lo);
    cudaGetSymbolAddress((void**)&w9h, g_wt9_hi);
    cudaGetSymbolAddress((void**)&w9l, g_wt9_lo);
    cudaGetSymbolAddress((void**)&wdh, g_wtd_hi);
    cudaGetSymbolAddress((void**)&wdl, g_wtd_lo);

    cudaFuncSetAttribute(k_gemm_mma<0>, cudaFuncAttributeMaxDynamicSharedMemorySize, SMEM_TOTAL);
    cudaFuncSetAttribute(k_gemm_mma<1>, cudaFuncAttributeMaxDynamicSharedMemorySize, SMEM_TOTAL);
    cudaFuncSetAttribute(k_gemm_mma<2>, cudaFuncAttributeMaxDynamicSharedMemorySize, SMEM_TOTAL);

    // CSR build + weight/x prep
    k_zero<<<(NN + 255) / 256, 256>>>();
    k_hist<<<NE / 256, 256>>>(edst);
    k_scan1<<<98, 256>>>();
    k_scan2<<<1, 128>>>(98);
    k_scan3<<<98, 256>>>();
    k_scatter<<<NE / 256, 256>>>(esrc, edst, ew);
    k_wprep9<<<(9 * 512 * 256 + 255) / 256, 256>>>(Wfc, convw);
    k_wprepd<<<(NL * 256 * 256 + 255) / 256, 256>>>(dynw);
    k_convx<<<(NN * 512 + 255) / 256, 256>>>(x);

    const int BIGK = 1 << 30;
    dim3 grid(2, GRID_M);

    // fc: h = h0 = relu(x@Wfc + bfc)
    k_gemm_mma<0><<<grid, 256, SMEM_TOTAL>>>(
        bxh, bxl, 512, (const __nv_bfloat16*)nullptr, (const __nv_bfloat16*)nullptr, 0,
        BIGK, 512, w9h, w9l,
        hf, bfc, nullptr, nullptr, nullptr, 0.f, 0.f,
        bh0h, bh0l, h0f);

    for (int i = 0; i < NL; i++) {
        k_spmm<<<NN / 8, 256>>>(hf, hif, bhih, bhil);
        float theta = logf(0.5f / (float)(i + 1) + 1.0f);
        k_gemm_mma<1><<<grid, 256, SMEM_TOTAL>>>(
            bhih, bhil, 256, bh0h, bh0l, 256,
            256, 512, w9h + (size_t)(1 + i) * 256 * 512, w9l + (size_t)(1 + i) * 256 * 512,
            hf, nullptr, hif, h0f, hf, theta, 0.f,
            nullptr, nullptr, nullptr);

        const __nv_bfloat16* dinh = (i == 0) ? bh0h : ((i & 1) ? bdAh : bdBh);
        const __nv_bfloat16* dinl = (i == 0) ? bh0l : ((i & 1) ? bdAl : bdBl);
        __nv_bfloat16* douh = (i & 1) ? bdBh : bdAh;
        __nv_bfloat16* doul = (i & 1) ? bdBl : bdAl;
        k_gemm_mma<2><<<grid, 256, SMEM_TOTAL>>>(
            dinh, dinl, 256, (const __nv_bfloat16*)nullptr, (const __nv_bfloat16*)nullptr, 0,
            BIGK, 256, wdh + (size_t)i * 256 * 256, wdl + (size_t)i * 256 * 256,
            df, dynb + (size_t)i * H, nullptr, h0f, nullptr, 0.f, (i > 0) ? 0.1f : 0.f,
            douh, doul, nullptr);
    }

    float* cross_out_ptr = (out_size >= NN * (NC + H)) ? (out + (size_t)NN * NC) : nullptr;
    k_cross<<<NN / 8, 256>>>(hf, df, g1, b1, g2, b2, hif /*scratch*/, cross_out_ptr);
    k_out<<<NN / 8, 256>>>(hif, Wout, bout, out);
}

// round 6
// speedup vs baseline: 1.4519x; 1.0694x over previous
#include <cuda_runtime.h>
#include <cuda_bf16.h>
#include <math.h>
#include <stdint.h>

#define NN 100000
#define NE 3200000
#define H  256
#define NC 40
#define NL 8
#define MPAD 100096          // 782 * 128
#define GRID_M 782
#define NGEMMB 1564          // 2 * 782
#define NSPMMB 12500         // 100000 / 8
#define FUSED_GRID 14076     // covers both with %9 interleave

// ---------------- device scratch (no allocations allowed) ------------------
__device__ int   g_deg[NN];
__device__ int   g_cur[NN];
__device__ int   g_rowptr[NN + 1];
__device__ int   g_bsums[128];
__device__ int   g_csrc[NE];
__device__ float g_cw[NE];

__device__ float g_h0f[MPAD * H];
__device__ float g_hf [MPAD * H];
__device__ float g_hif[MPAD * H];
__device__ float g_df [MPAD * H];

__device__ __nv_bfloat16 g_bx_hi[MPAD * 512];
__device__ __nv_bfloat16 g_bx_lo[MPAD * 512];
__device__ __nv_bfloat16 g_bh0_hi[MPAD * H];
__device__ __nv_bfloat16 g_bh0_lo[MPAD * H];
__device__ __nv_bfloat16 g_bhi_hi[MPAD * H];
__device__ __nv_bfloat16 g_bhi_lo[MPAD * H];
__device__ __nv_bfloat16 g_bdA_hi[MPAD * H];
__device__ __nv_bfloat16 g_bdA_lo[MPAD * H];
__device__ __nv_bfloat16 g_bdB_hi[MPAD * H];
__device__ __nv_bfloat16 g_bdB_lo[MPAD * H];

// weights, pre-transposed to [N=256][K] row-major, bf16 split
__device__ __nv_bfloat16 g_wt9_hi[9 * H * 512];   // fc + 8 conv (K=512)
__device__ __nv_bfloat16 g_wt9_lo[9 * H * 512];
__device__ __nv_bfloat16 g_wtd_hi[NL * H * H];    // dyn effective (K=256)
__device__ __nv_bfloat16 g_wtd_lo[NL * H * H];

// ---------------- helpers --------------------------------------------------
__device__ __forceinline__ uint32_t smem_u32(const void* p) {
    uint32_t a;
    asm("{ .reg .u64 t; cvta.to.shared.u64 t, %1; cvt.u32.u64 %0, t; }" : "=r"(a) : "l"(p));
    return a;
}
#define SW128(o) ((o) ^ (((o) >> 3) & 0x70))

__device__ __forceinline__ void cpasync16(uint32_t dst, const void* src, int srcsize) {
    uint64_t g = __cvta_generic_to_global(src);
    asm volatile("cp.async.cg.shared.global [%0], [%1], 16, %2;"
                 :: "r"(dst), "l"(g), "r"(srcsize) : "memory");
}
#define CP_COMMIT() asm volatile("cp.async.commit_group;" ::: "memory")
#define CP_WAIT0()  asm volatile("cp.async.wait_group 0;" ::: "memory")

__device__ __forceinline__ void ldx4(uint32_t* r, uint32_t addr) {
    asm volatile("ldmatrix.sync.aligned.m8n8.x4.shared.b16 {%0,%1,%2,%3}, [%4];"
                 : "=r"(r[0]), "=r"(r[1]), "=r"(r[2]), "=r"(r[3]) : "r"(addr));
}
__device__ __forceinline__ void ldx2(uint32_t* r, uint32_t addr) {
    asm volatile("ldmatrix.sync.aligned.m8n8.x2.shared.b16 {%0,%1}, [%2];"
                 : "=r"(r[0]), "=r"(r[1]) : "r"(addr));
}
__device__ __forceinline__ void mma16816(float* c, const uint32_t* a, const uint32_t* b) {
    asm volatile("mma.sync.aligned.m16n8k16.row.col.f32.bf16.bf16.f32 "
                 "{%0,%1,%2,%3}, {%4,%5,%6,%7}, {%8,%9}, {%0,%1,%2,%3};"
                 : "+f"(c[0]), "+f"(c[1]), "+f"(c[2]), "+f"(c[3])
                 : "r"(a[0]), "r"(a[1]), "r"(a[2]), "r"(a[3]), "r"(b[0]), "r"(b[1]));
}

// smem: single 64KB buffer: [Ahi 16K][Alo 16K][Bhi 16K][Blo 16K]
#define SMEM_TOTAL 65536

// ---------------- CSR build ------------------------------------------------
__global__ void k_zero() {
    int i = blockIdx.x * blockDim.x + threadIdx.x;
    if (i < NN) { g_deg[i] = 0; g_cur[i] = 0; }
}
__global__ void k_hist(const int* __restrict__ dst) {
    int e = blockIdx.x * blockDim.x + threadIdx.x;
    if (e < NE) atomicAdd(&g_deg[dst[e]], 1);
}
__global__ void k_scan1() {
    __shared__ int sh[256];
    int b = blockIdx.x, t = threadIdx.x;
    int base = b * 1024 + t * 4;
    int v[4], loc[4];
#pragma unroll
    for (int j = 0; j < 4; j++) { int idx = base + j; v[j] = (idx < NN) ? g_deg[idx] : 0; }
    loc[0] = v[0];
#pragma unroll
    for (int j = 1; j < 4; j++) loc[j] = loc[j - 1] + v[j];
    sh[t] = loc[3];
    __syncthreads();
    for (int off = 1; off < 256; off <<= 1) {
        int x = (t >= off) ? sh[t - off] : 0;
        __syncthreads();
        sh[t] += x;
        __syncthreads();
    }
    int pre = (t > 0) ? sh[t - 1] : 0;
#pragma unroll
    for (int j = 0; j < 4; j++) { int idx = base + j; if (idx < NN) g_rowptr[idx + 1] = pre + loc[j]; }
    if (t == 255) g_bsums[b] = sh[255];
}
__global__ void k_scan2(int nb) {
    __shared__ int sh[128];
    int t = threadIdx.x;
    sh[t] = (t < nb) ? g_bsums[t] : 0;
    __syncthreads();
    for (int off = 1; off < 128; off <<= 1) {
        int x = (t >= off) ? sh[t - off] : 0;
        __syncthreads();
        sh[t] += x;
        __syncthreads();
    }
    g_bsums[t] = sh[t];
}
__global__ void k_scan3() {
    int b = blockIdx.x, t = threadIdx.x;
    int add = (b > 0) ? g_bsums[b - 1] : 0;
#pragma unroll
    for (int j = 0; j < 4; j++) {
        int idx = b * 1024 + t * 4 + j;
        if (idx < NN) g_rowptr[idx + 1] += add;
    }
    if (b == 0 && t == 0) g_rowptr[0] = 0;
}
__global__ void k_scatter(const int* __restrict__ src, const int* __restrict__ dst,
                          const float* __restrict__ w) {
    int e = blockIdx.x * blockDim.x + threadIdx.x;
    if (e < NE) {
        int d = dst[e];
        int pos = g_rowptr[d] + atomicAdd(&g_cur[d], 1);
        g_csrc[pos] = src[e];
        g_cw[pos] = w[e];
    }
}

// ---------------- weight prep (transpose + bf16 split) ---------------------
__device__ __forceinline__ void bsplit(float v, __nv_bfloat16& hi, __nv_bfloat16& lo) {
    hi = __float2bfloat16_rn(v);
    lo = __float2bfloat16_rn(v - __bfloat162float(hi));
}
__global__ void k_wprep9(const float* __restrict__ Wfc, const float* __restrict__ convw) {
    int idx = blockIdx.x * blockDim.x + threadIdx.x;
    if (idx >= 9 * 512 * 256) return;
    int m = idx / (512 * 256);
    int r = idx - m * 512 * 256;
    int k = r / 256, n = r - k * 256;
    float v = (m == 0) ? Wfc[r] : convw[(m - 1) * 512 * 256 + r];
    __nv_bfloat16 hi, lo; bsplit(v, hi, lo);
    size_t o = (size_t)m * 256 * 512 + (size_t)n * 512 + k;
    g_wt9_hi[o] = hi; g_wt9_lo[o] = lo;
}
__global__ void k_wprepd(const float* __restrict__ dynw) {
    int idx = blockIdx.x * blockDim.x + threadIdx.x;
    if (idx >= NL * 256 * 256) return;
    int i = idx / (256 * 256);
    int r = idx - i * 256 * 256;
    int k = r / 256, n = r - k * 256;
    const float* base = dynw + (size_t)i * 512 * 256;
    float v = base[k * 256 + n] - base[(k + 256) * 256 + n];
    __nv_bfloat16 hi, lo; bsplit(v, hi, lo);
    size_t o = (size_t)i * 256 * 256 + (size_t)n * 256 + k;
    g_wtd_hi[o] = hi; g_wtd_lo[o] = lo;
}
__global__ void k_convx(const float* __restrict__ x) {
    int idx = blockIdx.x * blockDim.x + threadIdx.x;
    if (idx >= NN * 512) return;
    __nv_bfloat16 hi, lo; bsplit(x[idx], hi, lo);
    g_bx_hi[idx] = hi; g_bx_lo[idx] = lo;
}

// ---------------- warp-MMA GEMM block (device function) ---------------------
// C[M,256] = A[M,K] @ W^T, bf16 split (AhiBhi + AhiBlo + AloBhi), fp32 acc.
// MODE 0 fc  : v=relu(acc+bias); write C(hf), C2(h0f), Chi/Clo(bh0)
// MODE 1 conv: v=relu(theta*acc+(1-theta)*(0.9*Ehi+0.1*Eh0)+Eh); write C
// MODE 2 dyn : v=relu(acc+bias)+res*Eh0; write C(df), Chi/Clo
template <int MODE>
__device__ void gemm_block(
           int bx, int by,
           const __nv_bfloat16* __restrict__ A1h, const __nv_bfloat16* __restrict__ A1l, int s1,
           const __nv_bfloat16* __restrict__ A2h, const __nv_bfloat16* __restrict__ A2l, int s2,
           int K1, int K,
           const __nv_bfloat16* __restrict__ Bh, const __nv_bfloat16* __restrict__ Bl,
           float* __restrict__ C, const float* __restrict__ bias,
           const float* __restrict__ Ehi, const float* __restrict__ Eh0, const float* __restrict__ Eh,
           float theta, float res_scale,
           __nv_bfloat16* __restrict__ Chi, __nv_bfloat16* __restrict__ Clo,
           float* __restrict__ C2)
{
    extern __shared__ char smc[];
    uint32_t sb = smem_u32(smc);
    int t = threadIdx.x, lane = t & 31, wid = t >> 5;
    int widm = wid >> 2, widn = wid & 3;   // 2 x 4 warp grid
    int bn0 = bx * 128;
    int bm0 = by * 128;

    float acc[4][4][4];
#pragma unroll
    for (int a = 0; a < 4; a++)
#pragma unroll
        for (int b = 0; b < 4; b++)
#pragma unroll
            for (int c = 0; c < 4; c++) acc[a][b][c] = 0.f;

    const int nc = K / 64;

    int mi = lane >> 3;
    int arow_off = (lane & 7) + ((mi & 1) << 3);
    int akcol = (mi >> 1) << 4;
    int brow_off = (lane & 7);
    int bkcol = ((lane >> 3) & 1) << 4;

    for (int c = 0; c < nc; c++) {
        // ---- load chunk c into the single 64KB buffer ----
        {
            int kk0 = c * 64;
#pragma unroll
            for (int j = 0; j < 4; j++) {
                int idx = t + j * 256;
                int row = idx >> 3, c16 = idx & 7;
                uint32_t d = SW128(row * 128 + c16 * 16);
                int grow = bm0 + row;
                int kk = kk0 + c16 * 8;
                const __nv_bfloat16 *ph, *pl; int st;
                if (kk < K1) { ph = A1h; pl = A1l; st = s1; }
                else         { ph = A2h; pl = A2l; st = s2; kk -= K1; }
                int pred = 16;
                if (grow >= NN) { grow = 0; pred = 0; }
                cpasync16(sb + d,         ph + (size_t)grow * st + kk, pred);
                cpasync16(sb + 16384 + d, pl + (size_t)grow * st + kk, pred);
                int kkb = kk0 + c16 * 8;
                size_t bo = (size_t)(bn0 + row) * K + kkb;
                cpasync16(sb + 32768 + d, Bh + bo, 16);
                cpasync16(sb + 49152 + d, Bl + bo, 16);
            }
            CP_COMMIT();
        }
        CP_WAIT0();
        __syncthreads();
        // ---- compute chunk ----
#pragma unroll
        for (int ks = 0; ks < 4; ks++) {
            int kb = ks * 32;
            uint32_t Bh2[4][2], Bl2[4][2];
#pragma unroll
            for (int nt = 0; nt < 4; nt++) {
                int row = widn * 32 + nt * 8 + brow_off;
                uint32_t bd = sb + 32768 + SW128(row * 128 + kb + bkcol);
                ldx2(Bh2[nt], bd);
                ldx2(Bl2[nt], bd + 16384);
            }
#pragma unroll
            for (int mt = 0; mt < 4; mt++) {
                uint32_t Ah[4], Al[4];
                int row = widm * 64 + mt * 16 + arow_off;
                uint32_t ad = sb + SW128(row * 128 + kb + akcol);
                ldx4(Ah, ad);
                ldx4(Al, ad + 16384);
#pragma unroll
                for (int nt = 0; nt < 4; nt++) {
                    mma16816(acc[mt][nt], Ah, Bh2[nt]);
                    mma16816(acc[mt][nt], Ah, Bl2[nt]);
                    mma16816(acc[mt][nt], Al, Bh2[nt]);
                }
            }
        }
        __syncthreads();
    }

    // ---- epilogue ----
#pragma unroll
    for (int mt = 0; mt < 4; mt++) {
#pragma unroll
        for (int nt = 0; nt < 4; nt++) {
            int cb = bn0 + widn * 32 + nt * 8 + (lane & 3) * 2;
#pragma unroll
            for (int half = 0; half < 2; half++) {
                int row = bm0 + widm * 64 + mt * 16 + (lane >> 2) + half * 8;
                if (row >= NN) continue;
                size_t rb = (size_t)row * H + cb;
                float v0 = acc[mt][nt][half * 2 + 0];
                float v1 = acc[mt][nt][half * 2 + 1];
                if (MODE == 0) {
                    v0 = fmaxf(v0 + bias[cb], 0.f);
                    v1 = fmaxf(v1 + bias[cb + 1], 0.f);
                } else if (MODE == 1) {
                    float2 e1 = *(const float2*)(Ehi + rb);
                    float2 e2 = *(const float2*)(Eh0 + rb);
                    float2 e3 = *(const float2*)(Eh + rb);
                    v0 = fmaxf(theta * v0 + (1.f - theta) * (0.9f * e1.x + 0.1f * e2.x) + e3.x, 0.f);
                    v1 = fmaxf(theta * v1 + (1.f - theta) * (0.9f * e1.y + 0.1f * e2.y) + e3.y, 0.f);
                } else {
                    float2 e2 = *(const float2*)(Eh0 + rb);
                    v0 = fmaxf(v0 + bias[cb], 0.f) + res_scale * e2.x;
                    v1 = fmaxf(v1 + bias[cb + 1], 0.f) + res_scale * e2.y;
                }
                *(float2*)(C + rb) = make_float2(v0, v1);
                if (MODE == 0) *(float2*)(C2 + rb) = make_float2(v0, v1);
                if (MODE == 0 || MODE == 2) {
                    union { uint32_t u; __nv_bfloat16 b[2]; } ph_, pl_;
                    __nv_bfloat16 h0b = __float2bfloat16_rn(v0);
                    __nv_bfloat16 h1b = __float2bfloat16_rn(v1);
                    ph_.b[0] = h0b; ph_.b[1] = h1b;
                    pl_.b[0] = __float2bfloat16_rn(v0 - __bfloat162float(h0b));
                    pl_.b[1] = __float2bfloat16_rn(v1 - __bfloat162float(h1b));
                    *(uint32_t*)(Chi + rb) = ph_.u;
                    *(uint32_t*)(Clo + rb) = pl_.u;
                }
            }
        }
    }
}

template <int MODE>
__global__ void __launch_bounds__(256, 2)
k_gemm(const __nv_bfloat16* A1h, const __nv_bfloat16* A1l, int s1,
       const __nv_bfloat16* A2h, const __nv_bfloat16* A2l, int s2,
       int K1, int K,
       const __nv_bfloat16* Bh, const __nv_bfloat16* Bl,
       float* C, const float* bias,
       const float* Ehi, const float* Eh0, const float* Eh,
       float theta, float res_scale,
       __nv_bfloat16* Chi, __nv_bfloat16* Clo, float* C2)
{
    gemm_block<MODE>(blockIdx.x, blockIdx.y, A1h, A1l, s1, A2h, A2l, s2, K1, K,
                     Bh, Bl, C, bias, Ehi, Eh0, Eh, theta, res_scale, Chi, Clo, C2);
}

// ---------------- SpMM block (device function) ------------------------------
__device__ void spmm_block(int node_base, const float* __restrict__ h,
                           float* __restrict__ hif,
                           __nv_bfloat16* __restrict__ bhih,
                           __nv_bfloat16* __restrict__ bhil) {
    int wid = threadIdx.x >> 5, lane = threadIdx.x & 31;
    int node = node_base + wid;
    if (node >= NN) return;
    int s0 = g_rowptr[node], s1 = g_rowptr[node + 1];
    float4 a0 = make_float4(0.f, 0.f, 0.f, 0.f);
    float4 a1 = make_float4(0.f, 0.f, 0.f, 0.f);
    const float4* h4 = (const float4*)h;
    int e = s0;
    for (; e + 3 < s1; e += 4) {
        int si[4]; float w[4];
#pragma unroll
        for (int u = 0; u < 4; u++) { si[u] = g_csrc[e + u]; w[u] = g_cw[e + u]; }
        float4 v0[4], v1[4];
#pragma unroll
        for (int u = 0; u < 4; u++) {
            const float4* p = h4 + (size_t)si[u] * 64;
            v0[u] = __ldg(p + lane);
            v1[u] = __ldg(p + lane + 32);
        }
#pragma unroll
        for (int u = 0; u < 4; u++) {
            a0.x += w[u] * v0[u].x; a0.y += w[u] * v0[u].y;
            a0.z += w[u] * v0[u].z; a0.w += w[u] * v0[u].w;
            a1.x += w[u] * v1[u].x; a1.y += w[u] * v1[u].y;
            a1.z += w[u] * v1[u].z; a1.w += w[u] * v1[u].w;
        }
    }
    for (; e < s1; e++) {
        int sA = g_csrc[e];
        float wA = g_cw[e];
        const float4* pA = h4 + (size_t)sA * 64;
        float4 vA0 = __ldg(pA + lane), vA1 = __ldg(pA + lane + 32);
        a0.x += wA * vA0.x; a0.y += wA * vA0.y; a0.z += wA * vA0.z; a0.w += wA * vA0.w;
        a1.x += wA * vA1.x; a1.y += wA * vA1.y; a1.z += wA * vA1.z; a1.w += wA * vA1.w;
    }
    float4* op = (float4*)hif + (size_t)node * 64;
    op[lane] = a0;
    op[lane + 32] = a1;
    size_t rb = (size_t)node * H;
    union { uint2 u; __nv_bfloat16 b[4]; } ph_, pl_;
    float va[4] = {a0.x, a0.y, a0.z, a0.w};
#pragma unroll
    for (int i = 0; i < 4; i++) {
        __nv_bfloat16 hb = __float2bfloat16_rn(va[i]);
        ph_.b[i] = hb; pl_.b[i] = __float2bfloat16_rn(va[i] - __bfloat162float(hb));
    }
    *(uint2*)(bhih + rb + lane * 4) = ph_.u;
    *(uint2*)(bhil + rb + lane * 4) = pl_.u;
    float vb[4] = {a1.x, a1.y, a1.z, a1.w};
#pragma unroll
    for (int i = 0; i < 4; i++) {
        __nv_bfloat16 hb = __float2bfloat16_rn(vb[i]);
        ph_.b[i] = hb; pl_.b[i] = __float2bfloat16_rn(vb[i] - __bfloat162float(hb));
    }
    *(uint2*)(bhih + rb + 128 + lane * 4) = ph_.u;
    *(uint2*)(bhil + rb + 128 + lane * 4) = pl_.u;
}

// ---------------- fused SpMM + dyn-GEMM launch ------------------------------
// every 9th block = dyn GEMM block (tensor-bound); rest = SpMM (L2-bound).
__global__ void __launch_bounds__(256, 2)
k_sd(const __nv_bfloat16* dinh, const __nv_bfloat16* dinl,
     const __nv_bfloat16* wdh, const __nv_bfloat16* wdl,
     float* df, const float* dynb, const float* h0f, float res_scale,
     __nv_bfloat16* douh, __nv_bfloat16* doul,
     const float* hf, float* hif, __nv_bfloat16* bhih, __nv_bfloat16* bhil)
{
    int bid = blockIdx.x;
    if (bid % 9 == 0) {
        int gid = bid / 9;
        if (gid < NGEMMB)
            gemm_block<2>(gid & 1, gid >> 1,
                          dinh, dinl, 256, (const __nv_bfloat16*)nullptr, (const __nv_bfloat16*)nullptr, 0,
                          1 << 30, 256, wdh, wdl,
                          df, dynb, nullptr, h0f, nullptr, 0.f, res_scale,
                          douh, doul, nullptr);
    } else {
        int sid = bid - bid / 9 - 1;
        if (sid < NSPMMB)
            spmm_block(sid * 8, hf, hif, bhih, bhil);
    }
}

// ---------------- LN cross + output ----------------------------------------
__device__ __forceinline__ float warp_sum(float v) {
#pragma unroll
    for (int off = 16; off; off >>= 1) v += __shfl_xor_sync(0xffffffffu, v, off);
    return v;
}

__global__ void __launch_bounds__(256) k_cross(
    const float* __restrict__ h, const float* __restrict__ d,
    const float* __restrict__ g1, const float* __restrict__ b1,
    const float* __restrict__ g2, const float* __restrict__ b2,
    float* __restrict__ crossbuf, float* __restrict__ cross_out)
{
    int row = blockIdx.x * 8 + (threadIdx.x >> 5);
    int lane = threadIdx.x & 31;
    if (row >= NN) return;
    size_t rb = (size_t)row * H;
    float hv[8], dv[8];
#pragma unroll
    for (int r = 0; r < 8; r++) {
        int k = lane + 32 * r;
        hv[r] = h[rb + k];
        dv[r] = d[rb + k];
    }
    float sh = 0.f, sd = 0.f;
#pragma unroll
    for (int r = 0; r < 8; r++) { sh += hv[r]; sd += dv[r]; }
    sh = warp_sum(sh); sd = warp_sum(sd);
    float m1 = sh * (1.f / 256.f), m2 = sd * (1.f / 256.f);
    float q1 = 0.f, q2 = 0.f;
#pragma unroll
    for (int r = 0; r < 8; r++) {
        float e1 = hv[r] - m1; q1 += e1 * e1;
        float e2 = dv[r] - m2; q2 += e2 * e2;
    }
    q1 = warp_sum(q1); q2 = warp_sum(q2);
    float i1 = rsqrtf(q1 * (1.f / 256.f) + 1e-6f);
    float i2 = rsqrtf(q2 * (1.f / 256.f) + 1e-6f);
#pragma unroll
    for (int r = 0; r < 8; r++) {
        int k = lane + 32 * r;
        float v = g1[k] * (hv[r] - m1) * i1 + b1[k] + g2[k] * (dv[r] - m2) * i2 + b2[k];
        crossbuf[rb + k] = v;
        if (cross_out) cross_out[rb + k] = v;
    }
}

__global__ void __launch_bounds__(256) k_out(
    const float* __restrict__ cross, const float* __restrict__ Wout,
    const float* __restrict__ bout, float* __restrict__ out)
{
    __shared__ float Ws[256 * 41];
    __shared__ float bs[NC];
    int t = threadIdx.x;
    for (int i = t; i < 256 * NC; i += 256) {
        int k = i / NC, c = i - k * NC;
        Ws[k * 41 + c] = Wout[i];
    }
    if (t < NC) bs[t] = bout[t];
    __syncthreads();

    int row = blockIdx.x * 8 + (t >> 5);
    int lane = t & 31;
    if (row >= NN) return;

    float acc[NC];
#pragma unroll
    for (int c = 0; c < NC; c++) acc[c] = 0.f;
    size_t rb = (size_t)row * H;
#pragma unroll
    for (int r = 0; r < 8; r++) {
        int k = lane + 32 * r;
        float v = cross[rb + k];
        const float* wr = &Ws[k * 41];
#pragma unroll
        for (int c = 0; c < NC; c++) acc[c] += v * wr[c];
    }
#pragma unroll
    for (int c = 0; c < NC; c++)
#pragma unroll
        for (int off = 16; off; off >>= 1) acc[c] += __shfl_xor_sync(0xffffffffu, acc[c], off);

    float m = -1e30f;
#pragma unroll
    for (int c = 0; c < NC; c++) { acc[c] += bs[c]; m = fmaxf(m, acc[c]); }
    float s = 0.f;
#pragma unroll
    for (int c = 0; c < NC; c++) s += expf(acc[c] - m);
    float lse = m + logf(s);
    float* o = out + (size_t)row * NC;
#pragma unroll
    for (int c = 0; c < NC; c++)
        if ((c & 31) == lane) o[c] = acc[c] - lse;
}

// ---------------- launch ---------------------------------------------------
extern "C" void kernel_launch(void* const* d_in, const int* in_sizes, int n_in,
                              void* d_out, int out_size)
{
    const float* x     = (const float*)d_in[0];
    const int*   esrc  = (const int*)d_in[1];
    const int*   edst  = (const int*)d_in[2];
    const float* ew    = (const float*)d_in[3];
    const float* Wfc   = (const float*)d_in[4];
    const float* bfc   = (const float*)d_in[5];
    const float* convw = (const float*)d_in[6];
    const float* dynw  = (const float*)d_in[7];
    const float* dynb  = (const float*)d_in[8];
    const float* g1    = (const float*)d_in[9];
    const float* b1    = (const float*)d_in[10];
    const float* g2    = (const float*)d_in[11];
    const float* b2    = (const float*)d_in[12];
    const float* Wout  = (const float*)d_in[13];
    const float* bout  = (const float*)d_in[14];
    float* out = (float*)d_out;

    float *h0f, *hf, *hif, *df;
    cudaGetSymbolAddress((void**)&h0f, g_h0f);
    cudaGetSymbolAddress((void**)&hf,  g_hf);
    cudaGetSymbolAddress((void**)&hif, g_hif);
    cudaGetSymbolAddress((void**)&df,  g_df);
    __nv_bfloat16 *bxh, *bxl, *bh0h, *bh0l, *bhih, *bhil, *bdAh, *bdAl, *bdBh, *bdBl, *w9h, *w9l, *wdh, *wdl;
    cudaGetSymbolAddress((void**)&bxh, g_bx_hi);
    cudaGetSymbolAddress((void**)&bxl, g_bx_lo);
    cudaGetSymbolAddress((void**)&bh0h, g_bh0_hi);
    cudaGetSymbolAddress((void**)&bh0l, g_bh0_lo);
    cudaGetSymbolAddress((void**)&bhih, g_bhi_hi);
    cudaGetSymbolAddress((void**)&bhil, g_bhi_lo);
    cudaGetSymbolAddress((void**)&bdAh, g_bdA_hi);
    cudaGetSymbolAddress((void**)&bdAl, g_bdA_lo);
    cudaGetSymbolAddress((void**)&bdBh, g_bdB_hi);
    cudaGetSymbolAddress((void**)&bdBl, g_bdB_lo);
    cudaGetSymbolAddress((void**)&w9h, g_wt9_hi);
    cudaGetSymbolAddress((void**)&w9l, g_wt9_lo);
    cudaGetSymbolAddress((void**)&wdh, g_wtd_hi);
    cudaGetSymbolAddress((void**)&wdl, g_wtd_lo);

    cudaFuncSetAttribute(k_gemm<0>, cudaFuncAttributeMaxDynamicSharedMemorySize, SMEM_TOTAL);
    cudaFuncSetAttribute(k_gemm<1>, cudaFuncAttributeMaxDynamicSharedMemorySize, SMEM_TOTAL);
    cudaFuncSetAttribute(k_sd,      cudaFuncAttributeMaxDynamicSharedMemorySize, SMEM_TOTAL);

    const int BIGK = 1 << 30;
    dim3 grid(2, GRID_M);

    // prep first (also puts fc GEMM at an early launch index for ncu)
    k_convx<<<(NN * 512 + 255) / 256, 256>>>(x);
    k_wprep9<<<(9 * 512 * 256 + 255) / 256, 256>>>(Wfc, convw);
    k_wprepd<<<(NL * 256 * 256 + 255) / 256, 256>>>(dynw);

    // fc: h = h0 = relu(x@Wfc + bfc)
    k_gemm<0><<<grid, 256, SMEM_TOTAL>>>(
        bxh, bxl, 512, (const __nv_bfloat16*)nullptr, (const __nv_bfloat16*)nullptr, 0,
        BIGK, 512, w9h, w9l,
        hf, bfc, nullptr, nullptr, nullptr, 0.f, 0.f,
        bh0h, bh0l, h0f);

    // CSR build (independent of fc)
    k_zero<<<(NN + 255) / 256, 256>>>();
    k_hist<<<NE / 256, 256>>>(edst);
    k_scan1<<<98, 256>>>();
    k_scan2<<<1, 128>>>(98);
    k_scan3<<<98, 256>>>();
    k_scatter<<<NE / 256, 256>>>(esrc, edst, ew);

    for (int i = 0; i < NL; i++) {
        const __nv_bfloat16* dinh = (i == 0) ? bh0h : ((i & 1) ? bdAh : bdBh);
        const __nv_bfloat16* dinl = (i == 0) ? bh0l : ((i & 1) ? bdAl : bdBl);
        __nv_bfloat16* douh = (i & 1) ? bdBh : bdAh;
        __nv_bfloat16* doul = (i & 1) ? bdBl : bdAl;

        // fused: SpMM(h -> hi) overlapped with dyn GEMM (d -> d_next)
        k_sd<<<FUSED_GRID, 256, SMEM_TOTAL>>>(
            dinh, dinl, wdh + (size_t)i * 256 * 256, wdl + (size_t)i * 256 * 256,
            df, dynb + (size_t)i * H, h0f, (i > 0) ? 0.1f : 0.f,
            douh, doul,
            hf, hif, bhih, bhil);

        float theta = logf(0.5f / (float)(i + 1) + 1.0f);
        k_gemm<1><<<grid, 256, SMEM_TOTAL>>>(
            bhih, bhil, 256, bh0h, bh0l, 256,
            256, 512, w9h + (size_t)(1 + i) * 256 * 512, w9l + (size_t)(1 + i) * 256 * 512,
            hf, nullptr, hif, h0f, hf, theta, 0.f,
            nullptr, nullptr, nullptr);
    }

    float* cross_out_ptr = (out_size >= NN * (NC + H)) ? (out + (size_t)NN * NC) : nullptr;
    k_cross<<<NN / 8, 256>>>(hf, df, g1, b1, g2, b2, hif /*scratch*/, cross_out_ptr);
    k_out<<<NN / 8, 256>>>(hif, Wout, bout, out);
}